// round 5
// baseline (speedup 1.0000x reference)
#include <cuda_runtime.h>
#include <cuda_bf16.h>
#include <cstdint>

#define NN   50000
#define EE   800000
#define HIN  256
#define HH   128
#define BNEPS 1e-5f

// ---------------- device scratch ----------------
__device__ int   g_degr[NN];
__device__ int   g_cnt[NN];
__device__ int   g_cursor[NN];
__device__ int   g_startv[NN + 1];
__device__ int   g_csr_rows[EE];
__device__ float g_dinv[NN];
__device__ float g_h[(size_t)NN * HH];     // fp32 layer activations (for BN stats)
__device__ float g_s[(size_t)NN * HH];     // pre-aggregation messages (fp32)
__device__ float g_sum[HIN];
__device__ float g_sumsq[HIN];
__device__ float g_bshift[HH];
__device__ __nv_bfloat16 g_ahi[(size_t)NN * HIN];   // split-bf16 A operand
__device__ __nv_bfloat16 g_alo[(size_t)NN * HIN];
__device__ __nv_bfloat16 g_bhi[HH * HIN];           // split-bf16 B, [N][K] K-major
__device__ __nv_bfloat16 g_blo[HH * HIN];

// ---------------- PTX helpers (baseline sm_80+ features only) ----------------
__device__ __forceinline__ uint32_t smem_u32(const void* p) {
    uint32_t a;
    asm("{ .reg .u64 t; cvta.to.shared.u64 t, %1; cvt.u32.u64 %0, t; }" : "=r"(a) : "l"(p));
    return a;
}
#define CP16(dst, src) \
    asm volatile("cp.async.cg.shared.global [%0], [%1], 16;" :: "r"(dst), "l"(src))
#define CP_COMMIT() asm volatile("cp.async.commit_group;" ::: "memory")
#define CP_WAIT1()  asm volatile("cp.async.wait_group 1;" ::: "memory")
#define LDSM_X4(r, addr) \
    asm volatile("ldmatrix.sync.aligned.m8n8.x4.shared.b16 {%0,%1,%2,%3}, [%4];" \
        : "=r"((r)[0]), "=r"((r)[1]), "=r"((r)[2]), "=r"((r)[3]) : "r"(addr))
#define MMA_BF16(c, a, b) \
    asm volatile("mma.sync.aligned.m16n8k16.row.col.f32.bf16.bf16.f32 " \
        "{%0,%1,%2,%3}, {%4,%5,%6,%7}, {%8,%9}, {%0,%1,%2,%3};" \
        : "+f"((c)[0]), "+f"((c)[1]), "+f"((c)[2]), "+f"((c)[3]) \
        : "r"((a)[0]), "r"((a)[1]), "r"((a)[2]), "r"((a)[3]), "r"((b)[0]), "r"((b)[1]))

// ---------------- CSR build ----------------
__global__ void k_zero_counts() {
    int i = blockIdx.x * blockDim.x + threadIdx.x;
    if (i < NN) { g_degr[i] = 0; g_cnt[i] = 0; g_cursor[i] = 0; }
}
__global__ void k_count(const int* __restrict__ ei) {
    int e = blockIdx.x * blockDim.x + threadIdx.x;
    if (e < EE) {
        atomicAdd(&g_degr[ei[e]], 1);
        atomicAdd(&g_cnt[ei[EE + e]], 1);
    }
}
__global__ void k_scan() {
    __shared__ int part[1024];
    int t = threadIdx.x;
    const int per = (NN + 1023) / 1024;
    int b = t * per, e = min(b + per, NN);
    int s = 0;
    for (int i = b; i < e; i++) s += g_cnt[i];
    part[t] = s;
    __syncthreads();
    for (int off = 1; off < 1024; off <<= 1) {
        int v = (t >= off) ? part[t - off] : 0;
        __syncthreads();
        part[t] += v;
        __syncthreads();
    }
    int base = (t == 0) ? 0 : part[t - 1];
    for (int i = b; i < e; i++) { g_startv[i] = base; base += g_cnt[i]; }
    if (t == 1023) g_startv[NN] = part[1023];
}
__global__ void k_fill(const int* __restrict__ ei) {
    int e = blockIdx.x * blockDim.x + threadIdx.x;
    if (e < EE) {
        int r = ei[e], c = ei[EE + e];
        int p = atomicAdd(&g_cursor[c], 1);
        g_csr_rows[g_startv[c] + p] = r;
    }
}
__global__ void k_dinv() {
    int i = blockIdx.x * blockDim.x + threadIdx.x;
    if (i < NN) g_dinv[i] = rsqrtf((float)g_degr[i] + 1.0f);
}

// ---------------- BN stats ----------------
__global__ void k_stats(const float* __restrict__ A, int C) {
    int j = threadIdx.x;
    int r0 = blockIdx.x * 128;
    int rend = min(r0 + 128, NN);
    float s = 0.f, ss = 0.f;
    for (int r = r0; r < rend; r++) {
        float v = A[(size_t)r * C + j];
        s += v; ss += v * v;
    }
    atomicAdd(&g_sum[j], s);
    atomicAdd(&g_sumsq[j], ss);
}

// ---------------- fold BN into weights; emit split-bf16 B^T ----------------
__global__ void k_fold(int K, const float* __restrict__ W,
                       const float* __restrict__ gam, const float* __restrict__ bet) {
    __shared__ float sc[HIN], sh[HIN];
    int t = threadIdx.x;             // 256 threads
    if (t < K) {
        float mu  = g_sum[t] * (1.0f / NN);
        float var = g_sumsq[t] * (1.0f / NN) - mu * mu;
        float a   = rsqrtf(var + BNEPS) * gam[t];
        sc[t] = a;
        sh[t] = bet[t] - mu * a;
    }
    __syncthreads();
    for (int idx = t; idx < K * HH; idx += 256) {
        int k = idx >> 7;            // W row
        int n = idx & 127;           // W col
        float v = sc[k] * W[idx];
        __nv_bfloat16 hi = __float2bfloat16(v);
        float lo = v - __bfloat162float(hi);
        g_bhi[(size_t)n * K + k] = hi;
        g_blo[(size_t)n * K + k] = __float2bfloat16(lo);
    }
    if (t < HH) {
        float acc = 0.f;
        for (int k = 0; k < K; k++) acc += sh[k] * W[k * HH + t];
        g_bshift[t] = acc;
    }
    g_sum[t] = 0.f;
    g_sumsq[t] = 0.f;
}

// ---------------- convert raw x -> split bf16 ----------------
__global__ void k_convx(const float* __restrict__ x) {
    size_t i = (size_t)blockIdx.x * blockDim.x + threadIdx.x;   // over NN*HIN/4
    float4 v = ((const float4*)x)[i];
    __nv_bfloat16 h0 = __float2bfloat16(v.x), h1 = __float2bfloat16(v.y);
    __nv_bfloat16 h2 = __float2bfloat16(v.z), h3 = __float2bfloat16(v.w);
    __nv_bfloat162* ph = (__nv_bfloat162*)g_ahi;
    __nv_bfloat162* pl = (__nv_bfloat162*)g_alo;
    ph[i * 2 + 0] = __nv_bfloat162(h0, h1);
    ph[i * 2 + 1] = __nv_bfloat162(h2, h3);
    pl[i * 2 + 0] = __nv_bfloat162(__float2bfloat16(v.x - __bfloat162float(h0)),
                                   __float2bfloat16(v.y - __bfloat162float(h1)));
    pl[i * 2 + 1] = __nv_bfloat162(__float2bfloat16(v.z - __bfloat162float(h2)),
                                   __float2bfloat16(v.w - __bfloat162float(h3)));
}

// ---------------- mma.sync split-bf16 GEMM ----------------
// g_s[row][0:128] = ((A @ Bfold^T) + bshift) * dinv[row]
// Block tile 128x128, 8 warps in 4x2 (warp tile 32(m) x 64(n)), KC=16 chunks.
// SMEM: 2 stages x (AH|AL|BH|BL), each tile 128 rows x 16 bf16, row stride 48B
// (conflict-free ldmatrix). 2 x 24KB = 48KB static.
#define RS   48
#define TSZ  (128 * RS)          // 6144 bytes per tile
#define STG  (4 * TSZ)           // 24576 bytes per stage

__global__ void __launch_bounds__(256) k_gemm_mma(int K) {
    __shared__ char smem[2 * STG];
    const int t    = threadIdx.x;
    const int wid  = t >> 5;
    const int lane = t & 31;
    const int wm   = wid & 3;          // 0..3 -> 32-row band
    const int wn   = wid >> 2;         // 0..1 -> 64-col band
    const int row0 = blockIdx.x * 128;
    const uint32_t sbase = smem_u32(smem);

    float c[2][8][4];
    #pragma unroll
    for (int mt = 0; mt < 2; mt++)
        #pragma unroll
        for (int nt = 0; nt < 8; nt++)
            #pragma unroll
            for (int q = 0; q < 4; q++) c[mt][nt][q] = 0.f;

    // per-thread load slot: r = t>>1 (0..127), h = t&1 (16B half)
    const int lr = t >> 1;
    const int lh = t & 1;
    const int ar = min(row0 + lr, NN - 1);
    const uint32_t so = lr * RS + lh * 16;

    const int nch = K >> 4;

    // prologue: chunk 0 -> stage 0
    {
        size_t ka = (size_t)ar * K + lh * 8;
        size_t kb = (size_t)lr * K + lh * 8;
        CP16(sbase + 0 * TSZ + so, g_ahi + ka);
        CP16(sbase + 1 * TSZ + so, g_alo + ka);
        CP16(sbase + 2 * TSZ + so, g_bhi + kb);
        CP16(sbase + 3 * TSZ + so, g_blo + kb);
    }
    CP_COMMIT();

    for (int kc = 0; kc < nch; kc++) {
        if (kc + 1 < nch) {
            uint32_t sb = sbase + ((kc + 1) & 1) * STG;
            size_t ka = (size_t)ar * K + (kc + 1) * 16 + lh * 8;
            size_t kb = (size_t)lr * K + (kc + 1) * 16 + lh * 8;
            CP16(sb + 0 * TSZ + so, g_ahi + ka);
            CP16(sb + 1 * TSZ + so, g_alo + ka);
            CP16(sb + 2 * TSZ + so, g_bhi + kb);
            CP16(sb + 3 * TSZ + so, g_blo + kb);
        }
        CP_COMMIT();
        CP_WAIT1();
        __syncthreads();

        uint32_t base = sbase + (kc & 1) * STG;
        // A fragments (hi/lo) for 2 m-tiles
        uint32_t ah[2][4], al[2][4];
        #pragma unroll
        for (int mt = 0; mt < 2; mt++) {
            uint32_t addr = base + (wm * 32 + mt * 16 + (lane & 15)) * RS + (lane >> 4) * 16;
            LDSM_X4(ah[mt], addr);
            LDSM_X4(al[mt], addr + TSZ);
        }
        // B fragments (hi/lo) for 8 n-tiles (pairs via x4)
        uint32_t bh[8][2], bl[8][2];
        #pragma unroll
        for (int p = 0; p < 4; p++) {
            uint32_t addr = base + 2 * TSZ + (wn * 64 + p * 16 + (lane & 15)) * RS + (lane >> 4) * 16;
            uint32_t rr[4];
            LDSM_X4(rr, addr);
            bh[2 * p][0] = rr[0]; bh[2 * p][1] = rr[2];
            bh[2 * p + 1][0] = rr[1]; bh[2 * p + 1][1] = rr[3];
            LDSM_X4(rr, addr + TSZ);
            bl[2 * p][0] = rr[0]; bl[2 * p][1] = rr[2];
            bl[2 * p + 1][0] = rr[1]; bl[2 * p + 1][1] = rr[3];
        }
        #pragma unroll
        for (int mt = 0; mt < 2; mt++)
            #pragma unroll
            for (int nt = 0; nt < 8; nt++) {
                MMA_BF16(c[mt][nt], ah[mt], bh[nt]);
                MMA_BF16(c[mt][nt], al[mt], bh[nt]);
                MMA_BF16(c[mt][nt], ah[mt], bl[nt]);
            }
        __syncthreads();
    }

    // epilogue: (acc + bshift[col]) * dinv[row] -> g_s
    float bsv[8][2];
    #pragma unroll
    for (int nt = 0; nt < 8; nt++) {
        int gc = wn * 64 + nt * 8 + (lane & 3) * 2;
        bsv[nt][0] = __ldg(&g_bshift[gc]);
        bsv[nt][1] = __ldg(&g_bshift[gc + 1]);
    }
    #pragma unroll
    for (int mt = 0; mt < 2; mt++) {
        int r0g = row0 + wm * 32 + mt * 16 + (lane >> 2);
        int r1g = r0g + 8;
        float dv0 = g_dinv[min(r0g, NN - 1)];
        float dv1 = g_dinv[min(r1g, NN - 1)];
        #pragma unroll
        for (int nt = 0; nt < 8; nt++) {
            int gc = wn * 64 + nt * 8 + (lane & 3) * 2;
            if (r0g < NN) {
                float2 v;
                v.x = (c[mt][nt][0] + bsv[nt][0]) * dv0;
                v.y = (c[mt][nt][1] + bsv[nt][1]) * dv0;
                *(float2*)(g_s + (size_t)r0g * HH + gc) = v;
            }
            if (r1g < NN) {
                float2 v;
                v.x = (c[mt][nt][2] + bsv[nt][0]) * dv1;
                v.y = (c[mt][nt][3] + bsv[nt][1]) * dv1;
                *(float2*)(g_s + (size_t)r1g * HH + gc) = v;
            }
        }
    }
}

// ---------------- gather-aggregate + emit next layer's split-bf16 A ----------------
__global__ void __launch_bounds__(256) k_gather(const float* __restrict__ bgcn,
                                                float* __restrict__ out, int write_hilo) {
    int node = (blockIdx.x * blockDim.x + threadIdx.x) >> 5;
    if (node >= NN) return;
    int lane = threadIdx.x & 31;
    const float4* __restrict__ s4 = (const float4*)g_s;

    float4 a0 = s4[(size_t)node * 32 + lane];   // self-loop
    float4 a1 = make_float4(0.f, 0.f, 0.f, 0.f);

    int beg = g_startv[node];
    int end = g_startv[node + 1];
    int k = beg;
    for (; k + 1 < end; k += 2) {
        int r0 = __ldg(&g_csr_rows[k]);
        int r1 = __ldg(&g_csr_rows[k + 1]);
        float4 v0 = s4[(size_t)r0 * 32 + lane];
        float4 v1 = s4[(size_t)r1 * 32 + lane];
        a0.x += v0.x; a0.y += v0.y; a0.z += v0.z; a0.w += v0.w;
        a1.x += v1.x; a1.y += v1.y; a1.z += v1.z; a1.w += v1.w;
    }
    if (k < end) {
        int r0 = __ldg(&g_csr_rows[k]);
        float4 v0 = s4[(size_t)r0 * 32 + lane];
        a0.x += v0.x; a0.y += v0.y; a0.z += v0.z; a0.w += v0.w;
    }

    float dv = g_dinv[node];
    float4 b = *(const float4*)(bgcn + lane * 4);
    float4 o;
    o.x = (a0.x + a1.x) * dv + b.x;
    o.y = (a0.y + a1.y) * dv + b.y;
    o.z = (a0.z + a1.z) * dv + b.z;
    o.w = (a0.w + a1.w) * dv + b.w;
    *(float4*)(out + (size_t)node * HH + lane * 4) = o;

    if (write_hilo) {
        __nv_bfloat16 h0 = __float2bfloat16(o.x), h1 = __float2bfloat16(o.y);
        __nv_bfloat16 h2 = __float2bfloat16(o.z), h3 = __float2bfloat16(o.w);
        size_t base = (size_t)node * HH + lane * 4;
        __nv_bfloat162* ph = (__nv_bfloat162*)(g_ahi + base);
        __nv_bfloat162* pl = (__nv_bfloat162*)(g_alo + base);
        ph[0] = __nv_bfloat162(h0, h1);
        ph[1] = __nv_bfloat162(h2, h3);
        pl[0] = __nv_bfloat162(__float2bfloat16(o.x - __bfloat162float(h0)),
                               __float2bfloat16(o.y - __bfloat162float(h1)));
        pl[1] = __nv_bfloat162(__float2bfloat16(o.z - __bfloat162float(h2)),
                               __float2bfloat16(o.w - __bfloat162float(h3)));
    }
}

// ---------------- launch ----------------
extern "C" void kernel_launch(void* const* d_in, const int* in_sizes, int n_in,
                              void* d_out, int out_size) {
    const float* x       = (const float*)d_in[0];
    const int*   ei      = (const int*)  d_in[1];
    const float* bnf_g   = (const float*)d_in[2];
    const float* bnf_b   = (const float*)d_in[3];
    const float* W_feat  = (const float*)d_in[4];
    const float* b_feat  = (const float*)d_in[5];
    const float* bn_g    = (const float*)d_in[6];
    const float* bn_b    = (const float*)d_in[7];
    const float* Ws      = (const float*)d_in[8];
    const float* bs      = (const float*)d_in[9];
    float* out = (float*)d_out;

    float* g_h_ptr;   cudaGetSymbolAddress((void**)&g_h_ptr, g_h);

    const int RB = (NN + 127) / 128;              // 391 tiles
    const int GB = (NN * 32 + 255) / 256;
    const int EB = (EE + 255) / 256;

    // CSR build (reused by all layers)
    k_zero_counts<<<(NN + 255) / 256, 256>>>();
    k_count<<<EB, 256>>>(ei);
    k_scan<<<1, 1024>>>();
    k_fill<<<EB, 256>>>(ei);
    k_dinv<<<(NN + 255) / 256, 256>>>();

    // feature layer
    k_stats<<<RB, HIN>>>(x, HIN);
    k_fold<<<1, 256>>>(HIN, W_feat, bnf_g, bnf_b);
    k_convx<<<(NN * HIN / 4 + 255) / 256, 256>>>(x);
    k_gemm_mma<<<RB, 256>>>(HIN);
    k_gather<<<GB, 256>>>(b_feat, g_h_ptr, 1);

    // 3 GCN layers
    for (int i = 0; i < 3; i++) {
        k_stats<<<RB, HH>>>(g_h_ptr, HH);
        k_fold<<<1, 256>>>(HH, Ws + (size_t)i * HH * HH, bn_g + i * HH, bn_b + i * HH);
        k_gemm_mma<<<RB, 256>>>(HH);
        k_gather<<<GB, 256>>>(bs + i * HH, (i == 2) ? out : g_h_ptr, (i < 2) ? 1 : 0);
    }
}

// round 7
// speedup vs baseline: 1.0940x; 1.0940x over previous
#include <cuda_runtime.h>
#include <cuda_bf16.h>
#include <cstdint>

#define NN   50000
#define EE   800000
#define HIN  256
#define HH   128
#define BNEPS 1e-5f

// ---------------- device scratch ----------------
__device__ int   g_degr[NN];
__device__ int   g_cnt[NN];
__device__ int   g_cursor[NN];
__device__ int   g_startv[NN + 1];
__device__ int   g_csr_rows[EE];
__device__ float g_dinv[NN];
__device__ float g_h[(size_t)NN * HH];     // fp32 layer activations
__device__ float g_s[(size_t)NN * HH];     // pre-aggregation messages
__device__ float g_sum[HIN];
__device__ float g_sumsq[HIN];
__device__ float g_Wp[HIN * HH];           // folded weight [k][n]
__device__ float g_bshift[HH];

// ---------------- packed fp32x2 helpers (B300 FFMA2 path) ----------------
__device__ __forceinline__ uint64_t pk2(float x, float y) {
    uint64_t r; asm("mov.b64 %0, {%1, %2};" : "=l"(r) : "f"(x), "f"(y)); return r;
}
__device__ __forceinline__ void upk2(float& x, float& y, uint64_t v) {
    asm("mov.b64 {%0, %1}, %2;" : "=f"(x), "=f"(y) : "l"(v));
}
__device__ __forceinline__ void ffma2(uint64_t& d, uint64_t a, uint64_t b) {
    asm("fma.rn.f32x2 %0, %1, %2, %0;" : "+l"(d) : "l"(a), "l"(b));
}

// ---------------- CSR build ----------------
__global__ void k_zero_counts() {
    int i = blockIdx.x * blockDim.x + threadIdx.x;
    if (i < NN) { g_degr[i] = 0; g_cnt[i] = 0; g_cursor[i] = 0; }
}
__global__ void k_count(const int* __restrict__ ei) {
    int e = blockIdx.x * blockDim.x + threadIdx.x;
    if (e < EE) {
        atomicAdd(&g_degr[ei[e]], 1);
        atomicAdd(&g_cnt[ei[EE + e]], 1);
    }
}
__global__ void k_scan() {
    __shared__ int part[1024];
    int t = threadIdx.x;
    const int per = (NN + 1023) / 1024;
    int b = t * per, e = min(b + per, NN);
    int s = 0;
    for (int i = b; i < e; i++) s += g_cnt[i];
    part[t] = s;
    __syncthreads();
    for (int off = 1; off < 1024; off <<= 1) {
        int v = (t >= off) ? part[t - off] : 0;
        __syncthreads();
        part[t] += v;
        __syncthreads();
    }
    int base = (t == 0) ? 0 : part[t - 1];
    for (int i = b; i < e; i++) { g_startv[i] = base; base += g_cnt[i]; }
    if (t == 1023) g_startv[NN] = part[1023];
}
__global__ void k_fill(const int* __restrict__ ei) {
    int e = blockIdx.x * blockDim.x + threadIdx.x;
    if (e < EE) {
        int r = ei[e], c = ei[EE + e];
        int p = atomicAdd(&g_cursor[c], 1);
        g_csr_rows[g_startv[c] + p] = r;
    }
}
__global__ void k_dinv() {
    int i = blockIdx.x * blockDim.x + threadIdx.x;
    if (i < NN) g_dinv[i] = rsqrtf((float)g_degr[i] + 1.0f);
}

// ---------------- BN stats for raw input x (K=256) ----------------
__global__ void k_stats(const float* __restrict__ A, int C) {
    int j = threadIdx.x;
    int r0 = blockIdx.x * 128;
    int rend = min(r0 + 128, NN);
    float s = 0.f, ss = 0.f;
    for (int r = r0; r < rend; r++) {
        float v = A[(size_t)r * C + j];
        s += v; ss += v * v;
    }
    atomicAdd(&g_sum[j], s);
    atomicAdd(&g_sumsq[j], ss);
}

// ---------------- fold BN into weights ----------------
__global__ void k_fold(int K, const float* __restrict__ W,
                       const float* __restrict__ gam, const float* __restrict__ bet) {
    __shared__ float sc[HIN], sh[HIN];
    int t = threadIdx.x;             // 256 threads
    if (t < K) {
        float mu  = g_sum[t] * (1.0f / NN);
        float var = g_sumsq[t] * (1.0f / NN) - mu * mu;
        float a   = rsqrtf(var + BNEPS) * gam[t];
        sc[t] = a;
        sh[t] = bet[t] - mu * a;
    }
    __syncthreads();
    for (int idx = t; idx < K * HH; idx += 256)
        g_Wp[idx] = sc[idx >> 7] * W[idx];
    if (t < HH) {
        float acc = 0.f;
        for (int k = 0; k < K; k++) acc += sh[k] * W[k * HH + t];
        g_bshift[t] = acc;
    }
    g_sum[t] = 0.f;
    g_sumsq[t] = 0.f;
}

// ---------------- fp32x2 SGEMM: g_s = ((A @ Wp) + bshift) * dinv[row] ----------------
// BM=128, BN=128, BK=16, 256 threads, 8x8 microtile (n-cols split tn / tn+64),
// register-double-buffered SMEM, packed FFMA2 inner loop.
__global__ void __launch_bounds__(256) k_gemm2(const float* __restrict__ A, int K) {
    __shared__ float As[2][16][128];
    __shared__ float Bs[2][16][128];
    const int t    = threadIdx.x;
    const int row0 = blockIdx.x * 128;
    const int tm   = (t >> 4) * 8;
    const int tn   = (t & 15) * 4;      // cols tn..tn+3 and 64+tn..64+tn+3

    uint64_t acc[8][4];
    #pragma unroll
    for (int i = 0; i < 8; i++)
        #pragma unroll
        for (int q = 0; q < 4; q++) acc[i][q] = 0ull;

    // load slots: A row = t>>1, two float4 at k-quads akq, akq+1
    const int ar  = min(row0 + (t >> 1), NN - 1);
    const int lr  = t >> 1;
    const int akq = (t & 1) * 2;
    const int bk  = t >> 4;             // B k-row 0..15
    const int bn  = (t & 15) * 2;       // B float4 slots bn, bn+1

    float4 pa[2], pb[2];
    const int nch = K >> 4;

    // prologue: chunk 0 loads
    pa[0] = *(const float4*)(A + (size_t)ar * K + akq * 4);
    pa[1] = *(const float4*)(A + (size_t)ar * K + akq * 4 + 4);
    pb[0] = *(const float4*)(g_Wp + (size_t)bk * HH + bn * 4);
    pb[1] = *(const float4*)(g_Wp + (size_t)bk * HH + bn * 4 + 4);
    #pragma unroll
    for (int j = 0; j < 2; j++) {
        As[0][(akq + j) * 4 + 0][lr] = (&pa[j].x)[0];
        As[0][(akq + j) * 4 + 1][lr] = (&pa[j].x)[1];
        As[0][(akq + j) * 4 + 2][lr] = (&pa[j].x)[2];
        As[0][(akq + j) * 4 + 3][lr] = (&pa[j].x)[3];
        *(float4*)&Bs[0][bk][(bn + j) * 4] = pb[j];
    }
    __syncthreads();

    for (int kc = 0; kc < nch; kc++) {
        const int cur = kc & 1;
        if (kc + 1 < nch) {
            int k0 = (kc + 1) * 16;
            pa[0] = *(const float4*)(A + (size_t)ar * K + k0 + akq * 4);
            pa[1] = *(const float4*)(A + (size_t)ar * K + k0 + akq * 4 + 4);
            pb[0] = *(const float4*)(g_Wp + (size_t)(k0 + bk) * HH + bn * 4);
            pb[1] = *(const float4*)(g_Wp + (size_t)(k0 + bk) * HH + bn * 4 + 4);
        }
        #pragma unroll
        for (int kk = 0; kk < 16; kk++) {
            float4 a0 = *(float4*)&As[cur][kk][tm];
            float4 a1 = *(float4*)&As[cur][kk][tm + 4];
            float4 b0 = *(float4*)&Bs[cur][kk][tn];
            float4 b1 = *(float4*)&Bs[cur][kk][64 + tn];
            uint64_t bb0 = pk2(b0.x, b0.y), bb1 = pk2(b0.z, b0.w);
            uint64_t bb2 = pk2(b1.x, b1.y), bb3 = pk2(b1.z, b1.w);
            float av[8] = {a0.x, a0.y, a0.z, a0.w, a1.x, a1.y, a1.z, a1.w};
            #pragma unroll
            for (int i = 0; i < 8; i++) {
                uint64_t aa = pk2(av[i], av[i]);
                ffma2(acc[i][0], aa, bb0);
                ffma2(acc[i][1], aa, bb1);
                ffma2(acc[i][2], aa, bb2);
                ffma2(acc[i][3], aa, bb3);
            }
        }
        if (kc + 1 < nch) {
            const int nxt = cur ^ 1;
            #pragma unroll
            for (int j = 0; j < 2; j++) {
                As[nxt][(akq + j) * 4 + 0][lr] = (&pa[j].x)[0];
                As[nxt][(akq + j) * 4 + 1][lr] = (&pa[j].x)[1];
                As[nxt][(akq + j) * 4 + 2][lr] = (&pa[j].x)[2];
                As[nxt][(akq + j) * 4 + 3][lr] = (&pa[j].x)[3];
                *(float4*)&Bs[nxt][bk][(bn + j) * 4] = pb[j];
            }
            __syncthreads();
        }
    }

    // epilogue: (acc + bshift) * dinv -> g_s; cols {tn..tn+3} and {64+tn..}
    float bs0 = __ldg(&g_bshift[tn + 0]), bs1 = __ldg(&g_bshift[tn + 1]);
    float bs2 = __ldg(&g_bshift[tn + 2]), bs3 = __ldg(&g_bshift[tn + 3]);
    float bs4 = __ldg(&g_bshift[64 + tn + 0]), bs5 = __ldg(&g_bshift[64 + tn + 1]);
    float bs6 = __ldg(&g_bshift[64 + tn + 2]), bs7 = __ldg(&g_bshift[64 + tn + 3]);
    #pragma unroll
    for (int i = 0; i < 8; i++) {
        int r = row0 + tm + i;
        if (r >= NN) break;
        float dv = g_dinv[r];
        float x0, x1, x2, x3, x4, x5, x6, x7;
        upk2(x0, x1, acc[i][0]);
        upk2(x2, x3, acc[i][1]);
        upk2(x4, x5, acc[i][2]);
        upk2(x6, x7, acc[i][3]);
        float4 v0, v1;
        v0.x = (x0 + bs0) * dv; v0.y = (x1 + bs1) * dv;
        v0.z = (x2 + bs2) * dv; v0.w = (x3 + bs3) * dv;
        v1.x = (x4 + bs4) * dv; v1.y = (x5 + bs5) * dv;
        v1.z = (x6 + bs6) * dv; v1.w = (x7 + bs7) * dv;
        *(float4*)(g_s + (size_t)r * HH + tn)      = v0;
        *(float4*)(g_s + (size_t)r * HH + 64 + tn) = v1;
    }
}

// ---------------- gather-aggregate + fused next-layer BN stats ----------------
// warp per node (grid-stride), float4 per lane; per-warp stats regs -> smem -> global.
__global__ void __launch_bounds__(256) k_gather(const float* __restrict__ bgcn,
                                                float* __restrict__ out, int do_stats) {
    const int lane = threadIdx.x & 31;
    const int wg   = (blockIdx.x * blockDim.x + threadIdx.x) >> 5;
    const int nw   = (gridDim.x * blockDim.x) >> 5;
    __shared__ float sS[128], sQ[128];
    if (threadIdx.x < 128) { sS[threadIdx.x] = 0.f; sQ[threadIdx.x] = 0.f; }
    __syncthreads();

    const float4* __restrict__ s4 = (const float4*)g_s;
    float4 b = *(const float4*)(bgcn + lane * 4);
    float4 stS = make_float4(0.f, 0.f, 0.f, 0.f);
    float4 stQ = make_float4(0.f, 0.f, 0.f, 0.f);

    for (int node = wg; node < NN; node += nw) {
        float4 a0 = s4[(size_t)node * 32 + lane];   // self-loop
        float4 a1 = make_float4(0.f, 0.f, 0.f, 0.f);
        int beg = g_startv[node];
        int end = g_startv[node + 1];
        int k = beg;
        for (; k + 1 < end; k += 2) {
            int r0 = __ldg(&g_csr_rows[k]);
            int r1 = __ldg(&g_csr_rows[k + 1]);
            float4 v0 = s4[(size_t)r0 * 32 + lane];
            float4 v1 = s4[(size_t)r1 * 32 + lane];
            a0.x += v0.x; a0.y += v0.y; a0.z += v0.z; a0.w += v0.w;
            a1.x += v1.x; a1.y += v1.y; a1.z += v1.z; a1.w += v1.w;
        }
        if (k < end) {
            int r0 = __ldg(&g_csr_rows[k]);
            float4 v0 = s4[(size_t)r0 * 32 + lane];
            a0.x += v0.x; a0.y += v0.y; a0.z += v0.z; a0.w += v0.w;
        }
        float dv = g_dinv[node];
        float4 o;
        o.x = (a0.x + a1.x) * dv + b.x;
        o.y = (a0.y + a1.y) * dv + b.y;
        o.z = (a0.z + a1.z) * dv + b.z;
        o.w = (a0.w + a1.w) * dv + b.w;
        *(float4*)(out + (size_t)node * HH + lane * 4) = o;
        if (do_stats) {
            stS.x += o.x; stS.y += o.y; stS.z += o.z; stS.w += o.w;
            stQ.x += o.x * o.x; stQ.y += o.y * o.y;
            stQ.z += o.z * o.z; stQ.w += o.w * o.w;
        }
    }

    if (do_stats) {
        atomicAdd(&sS[lane * 4 + 0], stS.x);
        atomicAdd(&sS[lane * 4 + 1], stS.y);
        atomicAdd(&sS[lane * 4 + 2], stS.z);
        atomicAdd(&sS[lane * 4 + 3], stS.w);
        atomicAdd(&sQ[lane * 4 + 0], stQ.x);
        atomicAdd(&sQ[lane * 4 + 1], stQ.y);
        atomicAdd(&sQ[lane * 4 + 2], stQ.z);
        atomicAdd(&sQ[lane * 4 + 3], stQ.w);
        __syncthreads();
        if (threadIdx.x < 128) {
            atomicAdd(&g_sum[threadIdx.x], sS[threadIdx.x]);
            atomicAdd(&g_sumsq[threadIdx.x], sQ[threadIdx.x]);
        }
    }
}

// ---------------- launch ----------------
extern "C" void kernel_launch(void* const* d_in, const int* in_sizes, int n_in,
                              void* d_out, int out_size) {
    const float* x       = (const float*)d_in[0];
    const int*   ei      = (const int*)  d_in[1];
    const float* bnf_g   = (const float*)d_in[2];
    const float* bnf_b   = (const float*)d_in[3];
    const float* W_feat  = (const float*)d_in[4];
    const float* b_feat  = (const float*)d_in[5];
    const float* bn_g    = (const float*)d_in[6];
    const float* bn_b    = (const float*)d_in[7];
    const float* Ws      = (const float*)d_in[8];
    const float* bs      = (const float*)d_in[9];
    float* out = (float*)d_out;

    float* g_h_ptr;   cudaGetSymbolAddress((void**)&g_h_ptr, g_h);

    const int RB = (NN + 127) / 128;              // 391 tiles
    const int GB = 782;                           // gather blocks (8 warps, ~8 nodes/warp)
    const int EB = (EE + 255) / 256;

    // CSR build (reused by all layers)
    k_zero_counts<<<(NN + 255) / 256, 256>>>();
    k_count<<<EB, 256>>>(ei);
    k_scan<<<1, 1024>>>();
    k_fill<<<EB, 256>>>(ei);
    k_dinv<<<(NN + 255) / 256, 256>>>();

    // feature layer: BN(256) fold + GEMM K=256 + gather(with stats for layer 0)
    k_stats<<<RB, HIN>>>(x, HIN);
    k_fold<<<1, 256>>>(HIN, W_feat, bnf_g, bnf_b);
    k_gemm2<<<RB, 256>>>(x, HIN);
    k_gather<<<GB, 256>>>(b_feat, g_h_ptr, 1);

    // 3 GCN layers, K=128
    for (int i = 0; i < 3; i++) {
        k_fold<<<1, 256>>>(HH, Ws + (size_t)i * HH * HH, bn_g + i * HH, bn_b + i * HH);
        k_gemm2<<<RB, 256>>>(g_h_ptr, HH);
        k_gather<<<GB, 256>>>(bs + i * HH, (i == 2) ? out : g_h_ptr, (i < 2) ? 1 : 0);
    }
}

// round 8
// speedup vs baseline: 1.1582x; 1.0586x over previous
#include <cuda_runtime.h>
#include <cuda_fp16.h>
#include <cstdint>

#define NN   50000
#define EE   800000
#define HIN  256
#define HH   128
#define BNEPS 1e-5f

// ---------------- device scratch ----------------
__device__ int    g_degr[NN];
__device__ int    g_cnt[NN];
__device__ int    g_cursor[NN];
__device__ int    g_startv[NN + 1];
__device__ int    g_csr_rows[EE];
__device__ float  g_dinv[NN];
__device__ float  g_h[(size_t)NN * HH];     // fp32 layer activations (GEMM A operand)
__device__ __half g_s[(size_t)NN * HH];     // pre-aggregation messages (fp16!)
__device__ float  g_sum[HIN];
__device__ float  g_sumsq[HIN];
__device__ float  g_Wp[HIN * HH];           // folded weight [k][n]
__device__ float  g_bshift[HH];

// ---------------- packed fp32x2 helpers ----------------
__device__ __forceinline__ uint64_t pk2(float x, float y) {
    uint64_t r; asm("mov.b64 %0, {%1, %2};" : "=l"(r) : "f"(x), "f"(y)); return r;
}
__device__ __forceinline__ void upk2(float& x, float& y, uint64_t v) {
    asm("mov.b64 {%0, %1}, %2;" : "=f"(x), "=f"(y) : "l"(v));
}
__device__ __forceinline__ void ffma2(uint64_t& d, uint64_t a, uint64_t b) {
    asm("fma.rn.f32x2 %0, %1, %2, %0;" : "+l"(d) : "l"(a), "l"(b));
}

// ---------------- CSR build ----------------
__global__ void k_zero_counts() {
    int i = blockIdx.x * blockDim.x + threadIdx.x;
    if (i < NN) { g_degr[i] = 0; g_cnt[i] = 0; g_cursor[i] = 0; }
}
__global__ void k_count(const int* __restrict__ ei) {
    int e = blockIdx.x * blockDim.x + threadIdx.x;
    if (e < EE) {
        atomicAdd(&g_degr[ei[e]], 1);
        atomicAdd(&g_cnt[ei[EE + e]], 1);
    }
}
__global__ void k_scan() {
    __shared__ int part[1024];
    int t = threadIdx.x;
    const int per = (NN + 1023) / 1024;
    int b = t * per, e = min(b + per, NN);
    int s = 0;
    for (int i = b; i < e; i++) s += g_cnt[i];
    part[t] = s;
    __syncthreads();
    for (int off = 1; off < 1024; off <<= 1) {
        int v = (t >= off) ? part[t - off] : 0;
        __syncthreads();
        part[t] += v;
        __syncthreads();
    }
    int base = (t == 0) ? 0 : part[t - 1];
    for (int i = b; i < e; i++) { g_startv[i] = base; base += g_cnt[i]; }
    if (t == 1023) g_startv[NN] = part[1023];
}
__global__ void k_fill(const int* __restrict__ ei) {
    int e = blockIdx.x * blockDim.x + threadIdx.x;
    if (e < EE) {
        int r = ei[e], c = ei[EE + e];
        int p = atomicAdd(&g_cursor[c], 1);
        g_csr_rows[g_startv[c] + p] = r;
    }
}
__global__ void k_dinv() {
    int i = blockIdx.x * blockDim.x + threadIdx.x;
    if (i < NN) g_dinv[i] = rsqrtf((float)g_degr[i] + 1.0f);
}

// ---------------- BN stats for raw input x (K=256) ----------------
__global__ void k_stats(const float* __restrict__ A, int C) {
    int j = threadIdx.x;
    int r0 = blockIdx.x * 128;
    int rend = min(r0 + 128, NN);
    float s = 0.f, ss = 0.f;
    for (int r = r0; r < rend; r++) {
        float v = A[(size_t)r * C + j];
        s += v; ss += v * v;
    }
    atomicAdd(&g_sum[j], s);
    atomicAdd(&g_sumsq[j], ss);
}

// ---------------- fold BN into weights ----------------
__global__ void k_fold(int K, const float* __restrict__ W,
                       const float* __restrict__ gam, const float* __restrict__ bet) {
    __shared__ float sc[HIN], sh[HIN];
    int t = threadIdx.x;             // 256 threads
    if (t < K) {
        float mu  = g_sum[t] * (1.0f / NN);
        float var = g_sumsq[t] * (1.0f / NN) - mu * mu;
        float a   = rsqrtf(var + BNEPS) * gam[t];
        sc[t] = a;
        sh[t] = bet[t] - mu * a;
    }
    __syncthreads();
    for (int idx = t; idx < K * HH; idx += 256)
        g_Wp[idx] = sc[idx >> 7] * W[idx];
    if (t < HH) {
        float acc = 0.f;
        for (int k = 0; k < K; k++) acc += sh[k] * W[k * HH + t];
        g_bshift[t] = acc;
    }
    g_sum[t] = 0.f;
    g_sumsq[t] = 0.f;
}

// ---------------- fp32x2 SGEMM: g_s(fp16) = ((A @ Wp) + bshift) * dinv[row] ----------------
__global__ void __launch_bounds__(256) k_gemm2(const float* __restrict__ A, int K) {
    __shared__ float As[2][16][128];
    __shared__ float Bs[2][16][128];
    const int t    = threadIdx.x;
    const int row0 = blockIdx.x * 128;
    const int tm   = (t >> 4) * 8;
    const int tn   = (t & 15) * 4;      // cols tn..tn+3 and 64+tn..64+tn+3

    uint64_t acc[8][4];
    #pragma unroll
    for (int i = 0; i < 8; i++)
        #pragma unroll
        for (int q = 0; q < 4; q++) acc[i][q] = 0ull;

    const int ar  = min(row0 + (t >> 1), NN - 1);
    const int lr  = t >> 1;
    const int akq = (t & 1) * 2;
    const int bk  = t >> 4;
    const int bn  = (t & 15) * 2;

    float4 pa[2], pb[2];
    const int nch = K >> 4;

    pa[0] = *(const float4*)(A + (size_t)ar * K + akq * 4);
    pa[1] = *(const float4*)(A + (size_t)ar * K + akq * 4 + 4);
    pb[0] = *(const float4*)(g_Wp + (size_t)bk * HH + bn * 4);
    pb[1] = *(const float4*)(g_Wp + (size_t)bk * HH + bn * 4 + 4);
    #pragma unroll
    for (int j = 0; j < 2; j++) {
        As[0][(akq + j) * 4 + 0][lr] = (&pa[j].x)[0];
        As[0][(akq + j) * 4 + 1][lr] = (&pa[j].x)[1];
        As[0][(akq + j) * 4 + 2][lr] = (&pa[j].x)[2];
        As[0][(akq + j) * 4 + 3][lr] = (&pa[j].x)[3];
        *(float4*)&Bs[0][bk][(bn + j) * 4] = pb[j];
    }
    __syncthreads();

    for (int kc = 0; kc < nch; kc++) {
        const int cur = kc & 1;
        if (kc + 1 < nch) {
            int k0 = (kc + 1) * 16;
            pa[0] = *(const float4*)(A + (size_t)ar * K + k0 + akq * 4);
            pa[1] = *(const float4*)(A + (size_t)ar * K + k0 + akq * 4 + 4);
            pb[0] = *(const float4*)(g_Wp + (size_t)(k0 + bk) * HH + bn * 4);
            pb[1] = *(const float4*)(g_Wp + (size_t)(k0 + bk) * HH + bn * 4 + 4);
        }
        #pragma unroll
        for (int kk = 0; kk < 16; kk++) {
            float4 a0 = *(float4*)&As[cur][kk][tm];
            float4 a1 = *(float4*)&As[cur][kk][tm + 4];
            float4 b0 = *(float4*)&Bs[cur][kk][tn];
            float4 b1 = *(float4*)&Bs[cur][kk][64 + tn];
            uint64_t bb0 = pk2(b0.x, b0.y), bb1 = pk2(b0.z, b0.w);
            uint64_t bb2 = pk2(b1.x, b1.y), bb3 = pk2(b1.z, b1.w);
            float av[8] = {a0.x, a0.y, a0.z, a0.w, a1.x, a1.y, a1.z, a1.w};
            #pragma unroll
            for (int i = 0; i < 8; i++) {
                uint64_t aa = pk2(av[i], av[i]);
                ffma2(acc[i][0], aa, bb0);
                ffma2(acc[i][1], aa, bb1);
                ffma2(acc[i][2], aa, bb2);
                ffma2(acc[i][3], aa, bb3);
            }
        }
        if (kc + 1 < nch) {
            const int nxt = cur ^ 1;
            #pragma unroll
            for (int j = 0; j < 2; j++) {
                As[nxt][(akq + j) * 4 + 0][lr] = (&pa[j].x)[0];
                As[nxt][(akq + j) * 4 + 1][lr] = (&pa[j].x)[1];
                As[nxt][(akq + j) * 4 + 2][lr] = (&pa[j].x)[2];
                As[nxt][(akq + j) * 4 + 3][lr] = (&pa[j].x)[3];
                *(float4*)&Bs[nxt][bk][(bn + j) * 4] = pb[j];
            }
            __syncthreads();
        }
    }

    // epilogue: (acc + bshift) * dinv -> fp16 g_s
    float bs0 = __ldg(&g_bshift[tn + 0]), bs1 = __ldg(&g_bshift[tn + 1]);
    float bs2 = __ldg(&g_bshift[tn + 2]), bs3 = __ldg(&g_bshift[tn + 3]);
    float bs4 = __ldg(&g_bshift[64 + tn + 0]), bs5 = __ldg(&g_bshift[64 + tn + 1]);
    float bs6 = __ldg(&g_bshift[64 + tn + 2]), bs7 = __ldg(&g_bshift[64 + tn + 3]);
    #pragma unroll
    for (int i = 0; i < 8; i++) {
        int r = row0 + tm + i;
        if (r >= NN) break;
        float dv = g_dinv[r];
        float x0, x1, x2, x3, x4, x5, x6, x7;
        upk2(x0, x1, acc[i][0]);
        upk2(x2, x3, acc[i][1]);
        upk2(x4, x5, acc[i][2]);
        upk2(x6, x7, acc[i][3]);
        __half2 h01 = __floats2half2_rn((x0 + bs0) * dv, (x1 + bs1) * dv);
        __half2 h23 = __floats2half2_rn((x2 + bs2) * dv, (x3 + bs3) * dv);
        __half2 h45 = __floats2half2_rn((x4 + bs4) * dv, (x5 + bs5) * dv);
        __half2 h67 = __floats2half2_rn((x6 + bs6) * dv, (x7 + bs7) * dv);
        uint2 u0, u1;
        *(__half2*)&u0.x = h01; *(__half2*)&u0.y = h23;
        *(__half2*)&u1.x = h45; *(__half2*)&u1.y = h67;
        *(uint2*)(g_s + (size_t)r * HH + tn)      = u0;
        *(uint2*)(g_s + (size_t)r * HH + 64 + tn) = u1;
    }
}

// ---------------- gather-aggregate (fp16 messages) + fused BN stats ----------------
__global__ void __launch_bounds__(256) k_gather(const float* __restrict__ bgcn,
                                                float* __restrict__ out, int do_stats) {
    const int lane = threadIdx.x & 31;
    const int wg   = (blockIdx.x * blockDim.x + threadIdx.x) >> 5;
    const int nw   = (gridDim.x * blockDim.x) >> 5;
    __shared__ float sS[128], sQ[128];
    if (threadIdx.x < 128) { sS[threadIdx.x] = 0.f; sQ[threadIdx.x] = 0.f; }
    __syncthreads();

    const uint2* __restrict__ s2 = (const uint2*)g_s;   // 32 uint2 per row (128 halves)
    float4 b = *(const float4*)(bgcn + lane * 4);
    float4 stS = make_float4(0.f, 0.f, 0.f, 0.f);
    float4 stQ = make_float4(0.f, 0.f, 0.f, 0.f);

    for (int node = wg; node < NN; node += nw) {
        uint2 vs = s2[(size_t)node * 32 + lane];        // self-loop
        float2 f0 = __half22float2(*(__half2*)&vs.x);
        float2 f1 = __half22float2(*(__half2*)&vs.y);
        float a0x = f0.x, a0y = f0.y, a0z = f1.x, a0w = f1.y;
        float a1x = 0.f, a1y = 0.f, a1z = 0.f, a1w = 0.f;

        int beg = g_startv[node];
        int end = g_startv[node + 1];
        int k = beg;
        for (; k + 1 < end; k += 2) {
            int r0 = __ldg(&g_csr_rows[k]);
            int r1 = __ldg(&g_csr_rows[k + 1]);
            uint2 v0 = s2[(size_t)r0 * 32 + lane];
            uint2 v1 = s2[(size_t)r1 * 32 + lane];
            float2 p0 = __half22float2(*(__half2*)&v0.x);
            float2 p1 = __half22float2(*(__half2*)&v0.y);
            float2 q0 = __half22float2(*(__half2*)&v1.x);
            float2 q1 = __half22float2(*(__half2*)&v1.y);
            a0x += p0.x; a0y += p0.y; a0z += p1.x; a0w += p1.y;
            a1x += q0.x; a1y += q0.y; a1z += q1.x; a1w += q1.y;
        }
        if (k < end) {
            int r0 = __ldg(&g_csr_rows[k]);
            uint2 v0 = s2[(size_t)r0 * 32 + lane];
            float2 p0 = __half22float2(*(__half2*)&v0.x);
            float2 p1 = __half22float2(*(__half2*)&v0.y);
            a0x += p0.x; a0y += p0.y; a0z += p1.x; a0w += p1.y;
        }
        float dv = g_dinv[node];
        float4 o;
        o.x = (a0x + a1x) * dv + b.x;
        o.y = (a0y + a1y) * dv + b.y;
        o.z = (a0z + a1z) * dv + b.z;
        o.w = (a0w + a1w) * dv + b.w;
        *(float4*)(out + (size_t)node * HH + lane * 4) = o;
        if (do_stats) {
            stS.x += o.x; stS.y += o.y; stS.z += o.z; stS.w += o.w;
            stQ.x += o.x * o.x; stQ.y += o.y * o.y;
            stQ.z += o.z * o.z; stQ.w += o.w * o.w;
        }
    }

    if (do_stats) {
        atomicAdd(&sS[lane * 4 + 0], stS.x);
        atomicAdd(&sS[lane * 4 + 1], stS.y);
        atomicAdd(&sS[lane * 4 + 2], stS.z);
        atomicAdd(&sS[lane * 4 + 3], stS.w);
        atomicAdd(&sQ[lane * 4 + 0], stQ.x);
        atomicAdd(&sQ[lane * 4 + 1], stQ.y);
        atomicAdd(&sQ[lane * 4 + 2], stQ.z);
        atomicAdd(&sQ[lane * 4 + 3], stQ.w);
        __syncthreads();
        if (threadIdx.x < 128) {
            atomicAdd(&g_sum[threadIdx.x], sS[threadIdx.x]);
            atomicAdd(&g_sumsq[threadIdx.x], sQ[threadIdx.x]);
        }
    }
}

// ---------------- launch ----------------
extern "C" void kernel_launch(void* const* d_in, const int* in_sizes, int n_in,
                              void* d_out, int out_size) {
    const float* x       = (const float*)d_in[0];
    const int*   ei      = (const int*)  d_in[1];
    const float* bnf_g   = (const float*)d_in[2];
    const float* bnf_b   = (const float*)d_in[3];
    const float* W_feat  = (const float*)d_in[4];
    const float* b_feat  = (const float*)d_in[5];
    const float* bn_g    = (const float*)d_in[6];
    const float* bn_b    = (const float*)d_in[7];
    const float* Ws      = (const float*)d_in[8];
    const float* bs      = (const float*)d_in[9];
    float* out = (float*)d_out;

    float* g_h_ptr;   cudaGetSymbolAddress((void**)&g_h_ptr, g_h);

    const int RB = (NN + 127) / 128;              // 391 tiles
    const int GB = 782;
    const int EB = (EE + 255) / 256;

    // prep, reordered so launch #5 is the first GEMM (ncu window)
    k_zero_counts<<<(NN + 255) / 256, 256>>>();   // 0
    k_count<<<EB, 256>>>(ei);                     // 1
    k_dinv<<<(NN + 255) / 256, 256>>>();          // 2
    k_stats<<<RB, HIN>>>(x, HIN);                 // 3
    k_fold<<<1, 256>>>(HIN, W_feat, bnf_g, bnf_b);// 4
    k_gemm2<<<RB, 256>>>(x, HIN);                 // 5  <- ncu -s 5 target
    k_scan<<<1, 1024>>>();                        // 6
    k_fill<<<EB, 256>>>(ei);                      // 7
    k_gather<<<GB, 256>>>(b_feat, g_h_ptr, 1);    // 8

    // 3 GCN layers, K=128
    for (int i = 0; i < 3; i++) {
        k_fold<<<1, 256>>>(HH, Ws + (size_t)i * HH * HH, bn_g + i * HH, bn_b + i * HH);
        k_gemm2<<<RB, 256>>>(g_h_ptr, HH);
        k_gather<<<GB, 256>>>(bs + i * HH, (i == 2) ? out : g_h_ptr, (i < 2) ? 1 : 0);
    }
}

// round 9
// speedup vs baseline: 1.2310x; 1.0629x over previous
#include <cuda_runtime.h>
#include <cuda_fp16.h>
#include <cstdint>

#define NN   50000
#define EE   800000
#define HIN  256
#define HH   128
#define BNEPS 1e-5f

// ---------------- device scratch ----------------
__device__ int    g_degr[NN];
__device__ int    g_cnt[NN];
__device__ int    g_cursor[NN];
__device__ int    g_startv[NN + 1];
__device__ int    g_csr_rows[EE];
__device__ float  g_dinv[NN];
__device__ __half g_s[(size_t)NN * HH];      // pre-aggregation messages (fp16)
__device__ __half g_ah[(size_t)NN * HIN];    // A operand hi (fp16)
__device__ __half g_al[(size_t)NN * HIN];    // A operand lo (fp16)
__device__ __half g_w16[HH * HIN];           // folded weight fp16, [n][k] K-major
__device__ float  g_sum[HIN];
__device__ float  g_sumsq[HIN];
__device__ float  g_bshift[HH];

// ---------------- PTX helpers (baseline sm_80+ only) ----------------
__device__ __forceinline__ uint32_t smem_u32(const void* p) {
    uint32_t a;
    asm("{ .reg .u64 t; cvta.to.shared.u64 t, %1; cvt.u32.u64 %0, t; }" : "=r"(a) : "l"(p));
    return a;
}
#define CP16(dst, src) \
    asm volatile("cp.async.cg.shared.global [%0], [%1], 16;" :: "r"(dst), "l"(src))
#define CP_COMMIT() asm volatile("cp.async.commit_group;" ::: "memory")
#define CP_WAIT1()  asm volatile("cp.async.wait_group 1;" ::: "memory")
#define LDSM_X4(r, addr) \
    asm volatile("ldmatrix.sync.aligned.m8n8.x4.shared.b16 {%0,%1,%2,%3}, [%4];" \
        : "=r"((r)[0]), "=r"((r)[1]), "=r"((r)[2]), "=r"((r)[3]) : "r"(addr))
#define MMA_F16(c, a, b) \
    asm volatile("mma.sync.aligned.m16n8k16.row.col.f32.f16.f16.f32 " \
        "{%0,%1,%2,%3}, {%4,%5,%6,%7}, {%8,%9}, {%0,%1,%2,%3};" \
        : "+f"((c)[0]), "+f"((c)[1]), "+f"((c)[2]), "+f"((c)[3]) \
        : "r"((a)[0]), "r"((a)[1]), "r"((a)[2]), "r"((a)[3]), "r"((b)[0]), "r"((b)[1]))

// ---------------- CSR build ----------------
__global__ void k_zero_counts() {
    int i = blockIdx.x * blockDim.x + threadIdx.x;
    if (i < NN) { g_degr[i] = 0; g_cnt[i] = 0; g_cursor[i] = 0; }
}
__global__ void k_count(const int* __restrict__ ei) {
    int e = blockIdx.x * blockDim.x + threadIdx.x;
    if (e < EE) {
        atomicAdd(&g_degr[ei[e]], 1);
        atomicAdd(&g_cnt[ei[EE + e]], 1);
    }
}
__global__ void k_scan() {
    __shared__ int part[1024];
    int t = threadIdx.x;
    const int per = (NN + 1023) / 1024;
    int b = t * per, e = min(b + per, NN);
    int s = 0;
    for (int i = b; i < e; i++) s += g_cnt[i];
    part[t] = s;
    __syncthreads();
    for (int off = 1; off < 1024; off <<= 1) {
        int v = (t >= off) ? part[t - off] : 0;
        __syncthreads();
        part[t] += v;
        __syncthreads();
    }
    int base = (t == 0) ? 0 : part[t - 1];
    for (int i = b; i < e; i++) { g_startv[i] = base; base += g_cnt[i]; }
    if (t == 1023) g_startv[NN] = part[1023];
}
__global__ void k_fill(const int* __restrict__ ei) {
    int e = blockIdx.x * blockDim.x + threadIdx.x;
    if (e < EE) {
        int r = ei[e], c = ei[EE + e];
        int p = atomicAdd(&g_cursor[c], 1);
        g_csr_rows[g_startv[c] + p] = r;
    }
}
__global__ void k_dinv() {
    int i = blockIdx.x * blockDim.x + threadIdx.x;
    if (i < NN) g_dinv[i] = rsqrtf((float)g_degr[i] + 1.0f);
}

// ---------------- BN stats for raw input x (K=256) ----------------
__global__ void k_stats(const float* __restrict__ A, int C) {
    int j = threadIdx.x;
    int r0 = blockIdx.x * 128;
    int rend = min(r0 + 128, NN);
    float s = 0.f, ss = 0.f;
    for (int r = r0; r < rend; r++) {
        float v = A[(size_t)r * C + j];
        s += v; ss += v * v;
    }
    atomicAdd(&g_sum[j], s);
    atomicAdd(&g_sumsq[j], ss);
}

// ---------------- fold BN into weights; emit fp16 W^T + fp32 bshift ----------------
__global__ void k_fold(int K, const float* __restrict__ W,
                       const float* __restrict__ gam, const float* __restrict__ bet) {
    __shared__ float sc[HIN], sh[HIN];
    int t = threadIdx.x;             // 256 threads
    if (t < K) {
        float mu  = g_sum[t] * (1.0f / NN);
        float var = g_sumsq[t] * (1.0f / NN) - mu * mu;
        float a   = rsqrtf(var + BNEPS) * gam[t];
        sc[t] = a;
        sh[t] = bet[t] - mu * a;
    }
    __syncthreads();
    for (int idx = t; idx < K * HH; idx += 256) {
        int k = idx >> 7;            // W row
        int n = idx & 127;           // W col
        g_w16[(size_t)n * K + k] = __float2half_rn(sc[k] * W[idx]);
    }
    if (t < HH) {
        float acc = 0.f;
        for (int k = 0; k < K; k++) acc += sh[k] * W[k * HH + t];
        g_bshift[t] = acc;
    }
    g_sum[t] = 0.f;
    g_sumsq[t] = 0.f;
}

// ---------------- split raw x -> fp16 hi/lo ----------------
__global__ void k_convx(const float* __restrict__ x) {
    size_t i = (size_t)blockIdx.x * blockDim.x + threadIdx.x;   // over NN*HIN/4
    float4 v = ((const float4*)x)[i];
    __half h0 = __float2half_rn(v.x), h1 = __float2half_rn(v.y);
    __half h2 = __float2half_rn(v.z), h3 = __float2half_rn(v.w);
    __half2* ph = (__half2*)g_ah;
    __half2* pl = (__half2*)g_al;
    ph[i * 2 + 0] = __halves2half2(h0, h1);
    ph[i * 2 + 1] = __halves2half2(h2, h3);
    pl[i * 2 + 0] = __floats2half2_rn(v.x - __half2float(h0), v.y - __half2float(h1));
    pl[i * 2 + 1] = __floats2half2_rn(v.z - __half2float(h2), v.w - __half2float(h3));
}

// ---------------- 2-term fp16 HMMA GEMM ----------------
// g_s(fp16) = ((Ah + Al) @ W16^T + bshift) * dinv[row]
// Block tile 128x128, 8 warps 4x2, KC=16. SMEM: 2 stages x (AH|AL|W),
// each tile 128 rows x 16 fp16, row stride 48B (conflict-free ldmatrix). 36KB.
#define RS   48
#define TSZ  (128 * RS)          // 6144 bytes per tile
#define STG  (3 * TSZ)           // 18432 bytes per stage

__global__ void __launch_bounds__(256) k_gemm_h(int K) {
    __shared__ char smem[2 * STG];
    const int t    = threadIdx.x;
    const int wid  = t >> 5;
    const int lane = t & 31;
    const int wm   = wid & 3;          // 32-row band
    const int wn   = wid >> 2;         // 64-col band
    const int row0 = blockIdx.x * 128;
    const uint32_t sbase = smem_u32(smem);

    float c[2][8][4];
    #pragma unroll
    for (int mt = 0; mt < 2; mt++)
        #pragma unroll
        for (int nt = 0; nt < 8; nt++)
            #pragma unroll
            for (int q = 0; q < 4; q++) c[mt][nt][q] = 0.f;

    const int lr = t >> 1;
    const int lh = t & 1;
    const int ar = min(row0 + lr, NN - 1);
    const uint32_t so = lr * RS + lh * 16;
    const int nch = K >> 4;

    // prologue: chunk 0 -> stage 0
    {
        size_t ka = (size_t)ar * K + lh * 8;
        size_t kb = (size_t)lr * K + lh * 8;
        CP16(sbase + 0 * TSZ + so, g_ah + ka);
        CP16(sbase + 1 * TSZ + so, g_al + ka);
        CP16(sbase + 2 * TSZ + so, g_w16 + kb);
    }
    CP_COMMIT();

    for (int kc = 0; kc < nch; kc++) {
        if (kc + 1 < nch) {
            uint32_t sb = sbase + ((kc + 1) & 1) * STG;
            size_t ka = (size_t)ar * K + (kc + 1) * 16 + lh * 8;
            size_t kb = (size_t)lr * K + (kc + 1) * 16 + lh * 8;
            CP16(sb + 0 * TSZ + so, g_ah + ka);
            CP16(sb + 1 * TSZ + so, g_al + ka);
            CP16(sb + 2 * TSZ + so, g_w16 + kb);
        }
        CP_COMMIT();
        CP_WAIT1();
        __syncthreads();

        uint32_t base = sbase + (kc & 1) * STG;
        uint32_t ah[2][4], al[2][4];
        #pragma unroll
        for (int mt = 0; mt < 2; mt++) {
            uint32_t addr = base + (wm * 32 + mt * 16 + (lane & 15)) * RS + (lane >> 4) * 16;
            LDSM_X4(ah[mt], addr);
            LDSM_X4(al[mt], addr + TSZ);
        }
        uint32_t bw[8][2];
        #pragma unroll
        for (int p = 0; p < 4; p++) {
            uint32_t addr = base + 2 * TSZ + (wn * 64 + p * 16 + (lane & 15)) * RS + (lane >> 4) * 16;
            uint32_t rr[4];
            LDSM_X4(rr, addr);
            bw[2 * p][0] = rr[0]; bw[2 * p][1] = rr[2];
            bw[2 * p + 1][0] = rr[1]; bw[2 * p + 1][1] = rr[3];
        }
        #pragma unroll
        for (int mt = 0; mt < 2; mt++)
            #pragma unroll
            for (int nt = 0; nt < 8; nt++) {
                MMA_F16(c[mt][nt], ah[mt], bw[nt]);
                MMA_F16(c[mt][nt], al[mt], bw[nt]);
            }
        __syncthreads();
    }

    // epilogue: (acc + bshift[col]) * dinv[row] -> fp16 g_s
    float bsv[8][2];
    #pragma unroll
    for (int nt = 0; nt < 8; nt++) {
        int gc = wn * 64 + nt * 8 + (lane & 3) * 2;
        bsv[nt][0] = __ldg(&g_bshift[gc]);
        bsv[nt][1] = __ldg(&g_bshift[gc + 1]);
    }
    #pragma unroll
    for (int mt = 0; mt < 2; mt++) {
        int r0g = row0 + wm * 32 + mt * 16 + (lane >> 2);
        int r1g = r0g + 8;
        float dv0 = g_dinv[min(r0g, NN - 1)];
        float dv1 = g_dinv[min(r1g, NN - 1)];
        #pragma unroll
        for (int nt = 0; nt < 8; nt++) {
            int gc = wn * 64 + nt * 8 + (lane & 3) * 2;
            if (r0g < NN)
                *(__half2*)(g_s + (size_t)r0g * HH + gc) =
                    __floats2half2_rn((c[mt][nt][0] + bsv[nt][0]) * dv0,
                                      (c[mt][nt][1] + bsv[nt][1]) * dv0);
            if (r1g < NN)
                *(__half2*)(g_s + (size_t)r1g * HH + gc) =
                    __floats2half2_rn((c[mt][nt][2] + bsv[nt][0]) * dv1,
                                      (c[mt][nt][3] + bsv[nt][1]) * dv1);
        }
    }
}

// ---------------- gather-aggregate (fp16 msgs) -> fp16 hi/lo A + stats | fp32 out ----------------
__global__ void __launch_bounds__(256) k_gather(const float* __restrict__ bgcn,
                                                float* __restrict__ out, int final_layer) {
    const int lane = threadIdx.x & 31;
    const int wg   = (blockIdx.x * blockDim.x + threadIdx.x) >> 5;
    const int nw   = (gridDim.x * blockDim.x) >> 5;
    __shared__ float sS[128], sQ[128];
    if (threadIdx.x < 128) { sS[threadIdx.x] = 0.f; sQ[threadIdx.x] = 0.f; }
    __syncthreads();

    const uint2* __restrict__ s2 = (const uint2*)g_s;   // 32 uint2 per row
    float4 b = *(const float4*)(bgcn + lane * 4);
    float4 stS = make_float4(0.f, 0.f, 0.f, 0.f);
    float4 stQ = make_float4(0.f, 0.f, 0.f, 0.f);

    for (int node = wg; node < NN; node += nw) {
        uint2 vs = s2[(size_t)node * 32 + lane];        // self-loop
        float2 f0 = __half22float2(*(__half2*)&vs.x);
        float2 f1 = __half22float2(*(__half2*)&vs.y);
        float a0x = f0.x, a0y = f0.y, a0z = f1.x, a0w = f1.y;
        float a1x = 0.f, a1y = 0.f, a1z = 0.f, a1w = 0.f;

        int beg = g_startv[node];
        int end = g_startv[node + 1];
        int k = beg;
        for (; k + 1 < end; k += 2) {
            int r0 = __ldg(&g_csr_rows[k]);
            int r1 = __ldg(&g_csr_rows[k + 1]);
            uint2 v0 = s2[(size_t)r0 * 32 + lane];
            uint2 v1 = s2[(size_t)r1 * 32 + lane];
            float2 p0 = __half22float2(*(__half2*)&v0.x);
            float2 p1 = __half22float2(*(__half2*)&v0.y);
            float2 q0 = __half22float2(*(__half2*)&v1.x);
            float2 q1 = __half22float2(*(__half2*)&v1.y);
            a0x += p0.x; a0y += p0.y; a0z += p1.x; a0w += p1.y;
            a1x += q0.x; a1y += q0.y; a1z += q1.x; a1w += q1.y;
        }
        if (k < end) {
            int r0 = __ldg(&g_csr_rows[k]);
            uint2 v0 = s2[(size_t)r0 * 32 + lane];
            float2 p0 = __half22float2(*(__half2*)&v0.x);
            float2 p1 = __half22float2(*(__half2*)&v0.y);
            a0x += p0.x; a0y += p0.y; a0z += p1.x; a0w += p1.y;
        }
        float dv = g_dinv[node];
        float4 o;
        o.x = (a0x + a1x) * dv + b.x;
        o.y = (a0y + a1y) * dv + b.y;
        o.z = (a0z + a1z) * dv + b.z;
        o.w = (a0w + a1w) * dv + b.w;

        if (final_layer) {
            *(float4*)(out + (size_t)node * HH + lane * 4) = o;
        } else {
            // emit split-fp16 A for the next GEMM
            __half h0 = __float2half_rn(o.x), h1 = __float2half_rn(o.y);
            __half h2 = __float2half_rn(o.z), h3 = __float2half_rn(o.w);
            size_t base = (size_t)node * HH + lane * 4;
            __half2* ph = (__half2*)(g_ah + base);
            __half2* pl = (__half2*)(g_al + base);
            ph[0] = __halves2half2(h0, h1);
            ph[1] = __halves2half2(h2, h3);
            pl[0] = __floats2half2_rn(o.x - __half2float(h0), o.y - __half2float(h1));
            pl[1] = __floats2half2_rn(o.z - __half2float(h2), o.w - __half2float(h3));
            stS.x += o.x; stS.y += o.y; stS.z += o.z; stS.w += o.w;
            stQ.x += o.x * o.x; stQ.y += o.y * o.y;
            stQ.z += o.z * o.z; stQ.w += o.w * o.w;
        }
    }

    if (!final_layer) {
        atomicAdd(&sS[lane * 4 + 0], stS.x);
        atomicAdd(&sS[lane * 4 + 1], stS.y);
        atomicAdd(&sS[lane * 4 + 2], stS.z);
        atomicAdd(&sS[lane * 4 + 3], stS.w);
        atomicAdd(&sQ[lane * 4 + 0], stQ.x);
        atomicAdd(&sQ[lane * 4 + 1], stQ.y);
        atomicAdd(&sQ[lane * 4 + 2], stQ.z);
        atomicAdd(&sQ[lane * 4 + 3], stQ.w);
        __syncthreads();
        if (threadIdx.x < 128) {
            atomicAdd(&g_sum[threadIdx.x], sS[threadIdx.x]);
            atomicAdd(&g_sumsq[threadIdx.x], sQ[threadIdx.x]);
        }
    }
}

// ---------------- launch ----------------
extern "C" void kernel_launch(void* const* d_in, const int* in_sizes, int n_in,
                              void* d_out, int out_size) {
    const float* x       = (const float*)d_in[0];
    const int*   ei      = (const int*)  d_in[1];
    const float* bnf_g   = (const float*)d_in[2];
    const float* bnf_b   = (const float*)d_in[3];
    const float* W_feat  = (const float*)d_in[4];
    const float* b_feat  = (const float*)d_in[5];
    const float* bn_g    = (const float*)d_in[6];
    const float* bn_b    = (const float*)d_in[7];
    const float* Ws      = (const float*)d_in[8];
    const float* bs      = (const float*)d_in[9];
    float* out = (float*)d_out;

    const int RB = (NN + 127) / 128;              // 391 tiles
    const int GB = 782;
    const int EB = (EE + 255) / 256;

    // prep
    k_zero_counts<<<(NN + 255) / 256, 256>>>();   // 0
    k_count<<<EB, 256>>>(ei);                     // 1
    k_dinv<<<(NN + 255) / 256, 256>>>();          // 2
    k_stats<<<RB, HIN>>>(x, HIN);                 // 3
    k_fold<<<1, 256>>>(HIN, W_feat, bnf_g, bnf_b);// 4
    k_convx<<<(NN * HIN / 4 + 255) / 256, 256>>>(x); // 5
    k_gemm_h<<<RB, 256>>>(HIN);                   // 6
    k_scan<<<1, 1024>>>();                        // 7
    k_fill<<<EB, 256>>>(ei);                      // 8
    k_gather<<<GB, 256>>>(b_feat, nullptr, 0);    // 9

    // 3 GCN layers, K=128
    for (int i = 0; i < 3; i++) {
        k_fold<<<1, 256>>>(HH, Ws + (size_t)i * HH * HH, bn_g + i * HH, bn_b + i * HH);
        k_gemm_h<<<RB, 256>>>(HH);
        k_gather<<<GB, 256>>>(bs + i * HH, (i == 2) ? out : nullptr, (i == 2) ? 1 : 0);
    }
}